// round 2
// baseline (speedup 1.0000x reference)
#include <cuda_runtime.h>

// ---------------------------------------------------------------------------
// FourierConv: out[b,h,w,c] = bias[c] +
//   Re( ifft2( fft2(x[b,:,:,c], 255x255) * Keff[:,:,c] ) )[63:191, 63:191]
// where Keff[u,v,c] = sum_cout (kr + i*ki)[u,v,c,cout].
// Hermitian-folded: only u in [0,128) computed; Kh = (Keff + flipconj Keff)/2.
// ---------------------------------------------------------------------------

#define NF 255
#define NH 128
#define NC 16
#define NB 4
#define NIMG 64                  // NB * NC
#define PI2 6.28318530717958647692f

// Scratch (device globals: allocation-free rule)
__device__ float g_xT[NIMG*NH*NH];                 // x transposed: [img][w][h]
__device__ float g_Fr[NF*NH],  g_Fi[NF*NH];        // F[v][h] = exp(-2pi i v h/255)
__device__ float g_Gr[NH*NF],  g_Gi[NH*NF];        // G[w'][v] = exp(+2pi i v (w'+63)/255)
__device__ float g_Er[NH*NH],  g_Ei[NH*NH];        // E[h'][u] = c_u exp(+2pi i u (h'+63)/255)
__device__ float g_Ar[NIMG*NH*NH], g_Ai[NIMG*NH*NH];     // stage1 out [img][u][w]
__device__ float g_Xfr[NIMG*NH*NF], g_Xfi[NIMG*NH*NF];   // stage2 out [img][u][v]
__device__ float g_Keffr[NF*NF*NC], g_Keffi[NF*NF*NC];   // [u][v][c]
__device__ float g_Khr[NC*NH*NF],  g_Khi[NC*NH*NF];      // [c][u][v], scale folded
__device__ float g_Str[NIMG*NH*NH], g_Sti[NIMG*NH*NH];   // stage3 out TRANSPOSED [img][w'][u]

// ---------------------------------------------------------------------------
__global__ void k_twiddles() {
    int i = blockIdx.x * blockDim.x + threadIdx.x;
    const float w0 = PI2 / 255.0f;
    if (i < NF*NH) {                       // F: forward DFT matrix
        int v = i / NH, h = i % NH;
        int p = (v * h) % NF;
        float a = w0 * (float)p;
        g_Fr[i] = cosf(a);
        g_Fi[i] = -sinf(a);
        return;
    }
    int j = i - NF*NH;
    if (j < NH*NF) {                       // G: inverse (w' axis), crop offset 63
        int wq = j / NF, v = j % NF;
        int p = (v * (wq + 63)) % NF;
        float a = w0 * (float)p;
        g_Gr[j] = cosf(a);
        g_Gi[j] = sinf(a);
        return;
    }
    int e = j - NH*NF;
    if (e < NH*NH) {                       // E: inverse (h' axis), Hermitian weight c_u
        int h = e / NH, u = e % NH;
        int p = (u * (h + 63)) % NF;
        float a = w0 * (float)p;
        float cu = (u == 0) ? 1.0f : 2.0f;
        g_Er[e] = cu * cosf(a);
        g_Ei[e] = cu * sinf(a);
    }
}

// in[b][h][w][c] -> g_xT[(b*16+c)][w][h]
__global__ void k_transpose(const float* __restrict__ in) {
    int idx = blockIdx.x * blockDim.x + threadIdx.x;
    if (idx >= NIMG*NH*NH) return;
    int c = idx & 15;
    int w = (idx >> 4) & 127;
    int h = (idx >> 11) & 127;
    int b = idx >> 18;
    g_xT[((b*NC + c)*NH + w)*NH + h] = in[idx];
}

// Keff[u][v][c] = sum_cout k[u][v][c][cout]
__global__ void k_keff(const float* __restrict__ kr, const float* __restrict__ ki) {
    int idx = blockIdx.x * blockDim.x + threadIdx.x;   // uv*16 + cin
    if (idx >= NF*NF*NC) return;
    const float4* pr = (const float4*)(kr + (size_t)idx * 16);
    const float4* pi = (const float4*)(ki + (size_t)idx * 16);
    float sr = 0.f, si = 0.f;
#pragma unroll
    for (int j = 0; j < 4; j++) {
        float4 a = pr[j], b = pi[j];
        sr += a.x + a.y + a.z + a.w;
        si += b.x + b.y + b.z + b.w;
    }
    g_Keffr[idx] = sr;
    g_Keffi[idx] = si;
}

// Kh[c][u][v] = (Keff[u,v,c] + conj(Keff[-u,-v,c])) * 0.5 / 255^2
__global__ void k_kh() {
    int idx = blockIdx.x * blockDim.x + threadIdx.x;   // c*128*255 + u*255 + v
    if (idx >= NC*NH*NF) return;
    int v = idx % NF;
    int u = (idx / NF) % NH;
    int c = idx / (NF * NH);
    int u2 = (NF - u) % NF;
    int v2 = (NF - v) % NF;
    float ar = g_Keffr[(u *NF + v )*NC + c];
    float ai = g_Keffi[(u *NF + v )*NC + c];
    float br = g_Keffr[(u2*NF + v2)*NC + c];
    float bi = g_Keffi[(u2*NF + v2)*NC + c];
    const float s = 0.5f / 65025.0f;
    g_Khr[idx] = s * (ar + br);
    g_Khi[idx] = s * (ai - bi);
}

// ---------------------------------------------------------------------------
// Tiled GEMM stages. BM=BN=64, BK=16, 256 threads, 4x4 microtile.
// All GEMMs are "NT": C[m,n] = sum_k A[m,k] * B[n,k] (both K-contiguous).
// ---------------------------------------------------------------------------

// Stage1: A[img][u][w] = sum_h F[u][h] * xT[img][w][h]   (complex A, real B)
__global__ void k_stage1() {
    const int img = blockIdx.z;
    const int m0 = blockIdx.y * 64;   // u
    const int n0 = blockIdx.x * 64;   // w
    __shared__ __align__(16) float Asr[16][68], Asi[16][68], Bs[16][68];
    const float* Bg = g_xT + img * NH * NH;
    float accR[4][4] = {{0.f}}, accI[4][4] = {{0.f}};
    const int tid = threadIdx.x;
    const int tn = tid & 15, tm = tid >> 4;
    const int lk = tid & 15, lr = tid >> 4;
    for (int k0 = 0; k0 < NH; k0 += 16) {
#pragma unroll
        for (int r = 0; r < 4; r++) {
            int m = lr + r * 16;
            Asr[lk][m] = g_Fr[(m0 + m)*NH + k0 + lk];
            Asi[lk][m] = g_Fi[(m0 + m)*NH + k0 + lk];
            Bs [lk][m] = Bg[(n0 + m)*NH + k0 + lk];
        }
        __syncthreads();
#pragma unroll
        for (int k = 0; k < 16; k++) {
            float4 arv = *(const float4*)&Asr[k][tm*4];
            float4 aiv = *(const float4*)&Asi[k][tm*4];
            float4 bv  = *(const float4*)&Bs [k][tn*4];
            float ar[4] = {arv.x, arv.y, arv.z, arv.w};
            float ai[4] = {aiv.x, aiv.y, aiv.z, aiv.w};
            float bb[4] = {bv.x, bv.y, bv.z, bv.w};
#pragma unroll
            for (int i = 0; i < 4; i++)
#pragma unroll
                for (int j = 0; j < 4; j++) {
                    accR[i][j] += ar[i] * bb[j];
                    accI[i][j] += ai[i] * bb[j];
                }
        }
        __syncthreads();
    }
    float* Cr = g_Ar + img * NH * NH;
    float* Ci = g_Ai + img * NH * NH;
#pragma unroll
    for (int i = 0; i < 4; i++)
#pragma unroll
        for (int j = 0; j < 4; j++) {
            int m = m0 + tm*4 + i, n = n0 + tn*4 + j;
            Cr[m*NH + n] = accR[i][j];
            Ci[m*NH + n] = accI[i][j];
        }
}

// Stage2: Xf[img][u][v] = sum_w A[img][u][w] * F[v][w]   (complex x complex)
__global__ void k_stage2() {
    const int img = blockIdx.z;
    const int m0 = blockIdx.y * 64;   // u
    const int n0 = blockIdx.x * 64;   // v  (0..254)
    __shared__ __align__(16) float Asr[16][68], Asi[16][68], Bsr[16][68], Bsi[16][68];
    const float* Agr = g_Ar + img * NH * NH;
    const float* Agi = g_Ai + img * NH * NH;
    float accR[4][4] = {{0.f}}, accI[4][4] = {{0.f}};
    const int tid = threadIdx.x;
    const int tn = tid & 15, tm = tid >> 4;
    const int lk = tid & 15, lr = tid >> 4;
    for (int k0 = 0; k0 < NH; k0 += 16) {
#pragma unroll
        for (int r = 0; r < 4; r++) {
            int m = lr + r * 16;
            Asr[lk][m] = Agr[(m0 + m)*NH + k0 + lk];
            Asi[lk][m] = Agi[(m0 + m)*NH + k0 + lk];
            int n = n0 + m;
            float br = 0.f, bi = 0.f;
            if (n < NF) {
                br = g_Fr[n*NH + k0 + lk];
                bi = g_Fi[n*NH + k0 + lk];
            }
            Bsr[lk][m] = br;
            Bsi[lk][m] = bi;
        }
        __syncthreads();
#pragma unroll
        for (int k = 0; k < 16; k++) {
            float4 arv = *(const float4*)&Asr[k][tm*4];
            float4 aiv = *(const float4*)&Asi[k][tm*4];
            float4 brv = *(const float4*)&Bsr[k][tn*4];
            float4 biv = *(const float4*)&Bsi[k][tn*4];
            float ar[4] = {arv.x, arv.y, arv.z, arv.w};
            float ai[4] = {aiv.x, aiv.y, aiv.z, aiv.w};
            float br[4] = {brv.x, brv.y, brv.z, brv.w};
            float bi[4] = {biv.x, biv.y, biv.z, biv.w};
#pragma unroll
            for (int i = 0; i < 4; i++)
#pragma unroll
                for (int j = 0; j < 4; j++) {
                    accR[i][j] += ar[i]*br[j] - ai[i]*bi[j];
                    accI[i][j] += ar[i]*bi[j] + ai[i]*br[j];
                }
        }
        __syncthreads();
    }
    float* Cr = g_Xfr + img * NH * NF;
    float* Ci = g_Xfi + img * NH * NF;
#pragma unroll
    for (int i = 0; i < 4; i++)
#pragma unroll
        for (int j = 0; j < 4; j++) {
            int m = m0 + tm*4 + i, n = n0 + tn*4 + j;
            if (n < NF) {
                Cr[m*NF + n] = accR[i][j];
                Ci[m*NF + n] = accI[i][j];
            }
        }
}

// Stage3: St[img][w'][u] = sum_v (Xf[img][u][v]*Kh[c][u][v]) * G[w'][v]
// (pointwise Kh multiply fused into A-tile load; output stored transposed)
__global__ void k_stage3() {
    const int img = blockIdx.z;
    const int c = img & 15;
    const int m0 = blockIdx.y * 64;   // u
    const int n0 = blockIdx.x * 64;   // w'
    __shared__ __align__(16) float Asr[16][68], Asi[16][68], Bsr[16][68], Bsi[16][68];
    const float* Xr = g_Xfr + img * NH * NF;
    const float* Xi = g_Xfi + img * NH * NF;
    const float* Kr = g_Khr + c * NH * NF;
    const float* Ki = g_Khi + c * NH * NF;
    float accR[4][4] = {{0.f}}, accI[4][4] = {{0.f}};
    const int tid = threadIdx.x;
    const int tn = tid & 15, tm = tid >> 4;
    const int lk = tid & 15, lr = tid >> 4;
    for (int k0 = 0; k0 < 256; k0 += 16) {   // covers 255, last col padded
        int kk = k0 + lk;
        bool kok = (kk < NF);
#pragma unroll
        for (int r = 0; r < 4; r++) {
            int m = lr + r * 16;
            float yr = 0.f, yi = 0.f, gr = 0.f, gi = 0.f;
            if (kok) {
                int off = (m0 + m)*NF + kk;
                float xr = Xr[off], xi = Xi[off];
                float kr = Kr[off], ki = Ki[off];
                yr = xr*kr - xi*ki;
                yi = xr*ki + xi*kr;
                int goff = (n0 + m)*NF + kk;
                gr = g_Gr[goff];
                gi = g_Gi[goff];
            }
            Asr[lk][m] = yr; Asi[lk][m] = yi;
            Bsr[lk][m] = gr; Bsi[lk][m] = gi;
        }
        __syncthreads();
#pragma unroll
        for (int k = 0; k < 16; k++) {
            float4 arv = *(const float4*)&Asr[k][tm*4];
            float4 aiv = *(const float4*)&Asi[k][tm*4];
            float4 brv = *(const float4*)&Bsr[k][tn*4];
            float4 biv = *(const float4*)&Bsi[k][tn*4];
            float ar[4] = {arv.x, arv.y, arv.z, arv.w};
            float ai[4] = {aiv.x, aiv.y, aiv.z, aiv.w};
            float br[4] = {brv.x, brv.y, brv.z, brv.w};
            float bi[4] = {biv.x, biv.y, biv.z, biv.w};
#pragma unroll
            for (int i = 0; i < 4; i++)
#pragma unroll
                for (int j = 0; j < 4; j++) {
                    accR[i][j] += ar[i]*br[j] - ai[i]*bi[j];
                    accI[i][j] += ar[i]*bi[j] + ai[i]*br[j];
                }
        }
        __syncthreads();
    }
    float* Sr = g_Str + img * NH * NH;
    float* Si = g_Sti + img * NH * NH;
#pragma unroll
    for (int i = 0; i < 4; i++)
#pragma unroll
        for (int j = 0; j < 4; j++) {
            int u = m0 + tm*4 + i, w = n0 + tn*4 + j;
            Sr[w*NH + u] = accR[i][j];    // transposed store
            Si[w*NH + u] = accI[i][j];
        }
}

// Stage4: out[b][h][w][c] = bias[c] + sum_u (Er[h][u]*Str[w][u] - Ei[h][u]*Sti[w][u])
__global__ void k_stage4(const float* __restrict__ bias, float* __restrict__ out) {
    const int img = blockIdx.z;
    const int b = img >> 4, c = img & 15;
    const int m0 = blockIdx.y * 64;   // h
    const int n0 = blockIdx.x * 64;   // w
    __shared__ __align__(16) float Asr[16][68], Asi[16][68], Bsr[16][68], Bsi[16][68];
    const float* Sr = g_Str + img * NH * NH;
    const float* Si = g_Sti + img * NH * NH;
    float acc[4][4] = {{0.f}};
    const int tid = threadIdx.x;
    const int tn = tid & 15, tm = tid >> 4;
    const int lk = tid & 15, lr = tid >> 4;
    for (int k0 = 0; k0 < NH; k0 += 16) {
#pragma unroll
        for (int r = 0; r < 4; r++) {
            int m = lr + r * 16;
            Asr[lk][m] = g_Er[(m0 + m)*NH + k0 + lk];
            Asi[lk][m] = g_Ei[(m0 + m)*NH + k0 + lk];
            Bsr[lk][m] = Sr[(n0 + m)*NH + k0 + lk];
            Bsi[lk][m] = Si[(n0 + m)*NH + k0 + lk];
        }
        __syncthreads();
#pragma unroll
        for (int k = 0; k < 16; k++) {
            float4 arv = *(const float4*)&Asr[k][tm*4];
            float4 aiv = *(const float4*)&Asi[k][tm*4];
            float4 brv = *(const float4*)&Bsr[k][tn*4];
            float4 biv = *(const float4*)&Bsi[k][tn*4];
            float ar[4] = {arv.x, arv.y, arv.z, arv.w};
            float ai[4] = {aiv.x, aiv.y, aiv.z, aiv.w};
            float br[4] = {brv.x, brv.y, brv.z, brv.w};
            float bi[4] = {biv.x, biv.y, biv.z, biv.w};
#pragma unroll
            for (int i = 0; i < 4; i++)
#pragma unroll
                for (int j = 0; j < 4; j++) {
                    acc[i][j] += ar[i]*br[j] - ai[i]*bi[j];
                }
        }
        __syncthreads();
    }
    float bv = bias[c];
#pragma unroll
    for (int i = 0; i < 4; i++)
#pragma unroll
        for (int j = 0; j < 4; j++) {
            int h = m0 + tm*4 + i, w = n0 + tn*4 + j;
            out[((b*NH + h)*NH + w)*NC + c] = acc[i][j] + bv;
        }
}

// ---------------------------------------------------------------------------
extern "C" void kernel_launch(void* const* d_in, const int* in_sizes, int n_in,
                              void* d_out, int out_size) {
    const float* inp  = (const float*)d_in[0];
    const float* kr   = (const float*)d_in[1];
    const float* ki   = (const float*)d_in[2];
    const float* bias = (const float*)d_in[3];
    float* out = (float*)d_out;

    const int twN = NF*NH + NH*NF + NH*NH;          // 81664
    k_twiddles<<<(twN + 255) / 256, 256>>>();
    k_transpose<<<(NIMG*NH*NH + 255) / 256, 256>>>(inp);
    k_keff<<<(NF*NF*NC + 255) / 256, 256>>>(kr, ki);
    k_kh<<<(NC*NH*NF + 255) / 256, 256>>>();

    dim3 blk(256);
    dim3 g1(2, 2, NIMG); k_stage1<<<g1, blk>>>();
    dim3 g2(4, 2, NIMG); k_stage2<<<g2, blk>>>();
    dim3 g3(2, 2, NIMG); k_stage3<<<g3, blk>>>();
    dim3 g4(2, 2, NIMG); k_stage4<<<g4, blk>>>(bias, out);
}

// round 3
// speedup vs baseline: 1.0026x; 1.0026x over previous
#include <cuda_runtime.h>

// ---------------------------------------------------------------------------
// FourierConv: out[b,h,w,c] = bias[c] +
//   Re( ifft2( fft2(x[b,:,:,c], 255x255) * Keff[:,:,c] ) )[63:191, 63:191]
// where Keff[u,v,c] = sum_cout (kr + i*ki)[u,v,c,cout].
// Hermitian-folded: only u in [0,128) computed; Kh = (Keff + flipconj Keff)/2.
// ---------------------------------------------------------------------------

#define NF 255
#define NH 128
#define NC 16
#define NB 4
#define NIMG 64                  // NB * NC
#define PI2 6.28318530717958647692f

// Scratch (device globals: allocation-free rule)
__device__ float g_xT[NIMG*NH*NH];                 // x transposed: [img][w][h]
__device__ float g_Fr[NF*NH],  g_Fi[NF*NH];        // F[v][h] = exp(-2pi i v h/255)
__device__ float g_Gr[NH*NF],  g_Gi[NH*NF];        // G[w'][v] = exp(+2pi i v (w'+63)/255)
__device__ float g_Er[NH*NH],  g_Ei[NH*NH];        // E[h'][u] = c_u exp(+2pi i u (h'+63)/255)
__device__ float g_Ar[NIMG*NH*NH], g_Ai[NIMG*NH*NH];     // stage1 out [img][u][w]
__device__ float g_Xfr[NIMG*NH*NF], g_Xfi[NIMG*NH*NF];   // stage2 out [img][u][v]
__device__ float g_Keffr[NF*NF*NC], g_Keffi[NF*NF*NC];   // [u][v][c]
__device__ float g_Khr[NC*NH*NF],  g_Khi[NC*NH*NF];      // [c][u][v], scale folded
__device__ float g_Str[NIMG*NH*NH], g_Sti[NIMG*NH*NH];   // stage3 out TRANSPOSED [img][w'][u]

// ---------------------------------------------------------------------------
__global__ void k_twiddles() {
    int i = blockIdx.x * blockDim.x + threadIdx.x;
    const float w0 = PI2 / 255.0f;
    if (i < NF*NH) {                       // F: forward DFT matrix
        int v = i / NH, h = i % NH;
        int p = (v * h) % NF;
        float a = w0 * (float)p;
        g_Fr[i] = cosf(a);
        g_Fi[i] = -sinf(a);
        return;
    }
    int j = i - NF*NH;
    if (j < NH*NF) {                       // G: inverse (w' axis), crop offset 63
        int wq = j / NF, v = j % NF;
        int p = (v * (wq + 63)) % NF;
        float a = w0 * (float)p;
        g_Gr[j] = cosf(a);
        g_Gi[j] = sinf(a);
        return;
    }
    int e = j - NH*NF;
    if (e < NH*NH) {                       // E: inverse (h' axis), Hermitian weight c_u
        int h = e / NH, u = e % NH;
        int p = (u * (h + 63)) % NF;
        float a = w0 * (float)p;
        float cu = (u == 0) ? 1.0f : 2.0f;
        g_Er[e] = cu * cosf(a);
        g_Ei[e] = cu * sinf(a);
    }
}

// in[b][h][w][c] -> g_xT[(b*16+c)][w][h]
__global__ void k_transpose(const float* __restrict__ in) {
    int idx = blockIdx.x * blockDim.x + threadIdx.x;
    if (idx >= NIMG*NH*NH) return;
    int c = idx & 15;
    int w = (idx >> 4) & 127;
    int h = (idx >> 11) & 127;
    int b = idx >> 18;
    g_xT[((b*NC + c)*NH + w)*NH + h] = in[idx];
}

// Keff[u][v][c] = sum_cout k[u][v][c][cout]
__global__ void k_keff(const float* __restrict__ kr, const float* __restrict__ ki) {
    int idx = blockIdx.x * blockDim.x + threadIdx.x;   // uv*16 + cin
    if (idx >= NF*NF*NC) return;
    const float4* pr = (const float4*)(kr + (size_t)idx * 16);
    const float4* pi = (const float4*)(ki + (size_t)idx * 16);
    float sr = 0.f, si = 0.f;
#pragma unroll
    for (int j = 0; j < 4; j++) {
        float4 a = pr[j], b = pi[j];
        sr += a.x + a.y + a.z + a.w;
        si += b.x + b.y + b.z + b.w;
    }
    g_Keffr[idx] = sr;
    g_Keffi[idx] = si;
}

// Kh[c][u][v] = (Keff[u,v,c] + conj(Keff[-u,-v,c])) * 0.5 / 255^2
__global__ void k_kh() {
    int idx = blockIdx.x * blockDim.x + threadIdx.x;   // c*128*255 + u*255 + v
    if (idx >= NC*NH*NF) return;
    int v = idx % NF;
    int u = (idx / NF) % NH;
    int c = idx / (NF * NH);
    int u2 = (NF - u) % NF;
    int v2 = (NF - v) % NF;
    float ar = g_Keffr[(u *NF + v )*NC + c];
    float ai = g_Keffi[(u *NF + v )*NC + c];
    float br = g_Keffr[(u2*NF + v2)*NC + c];
    float bi = g_Keffi[(u2*NF + v2)*NC + c];
    const float s = 0.5f / 65025.0f;
    g_Khr[idx] = s * (ar + br);
    g_Khi[idx] = s * (ai - bi);
}

// ---------------------------------------------------------------------------
// Tiled GEMM stages. BM=BN=64, BK=16, 256 threads, 4x4 microtile.
// All GEMMs are "NT": C[m,n] = sum_k A[m,k] * B[n,k] (both K-contiguous).
// ---------------------------------------------------------------------------

// Stage1: A[img][u][w] = sum_h F[u][h] * xT[img][w][h]   (complex A, real B)
__global__ void k_stage1() {
    const int img = blockIdx.z;
    const int m0 = blockIdx.y * 64;   // u
    const int n0 = blockIdx.x * 64;   // w
    __shared__ __align__(16) float Asr[16][68], Asi[16][68], Bs[16][68];
    const float* Bg = g_xT + img * NH * NH;
    float accR[4][4] = {{0.f}}, accI[4][4] = {{0.f}};
    const int tid = threadIdx.x;
    const int tn = tid & 15, tm = tid >> 4;
    const int lk = tid & 15, lr = tid >> 4;
    for (int k0 = 0; k0 < NH; k0 += 16) {
#pragma unroll
        for (int r = 0; r < 4; r++) {
            int m = lr + r * 16;
            Asr[lk][m] = g_Fr[(m0 + m)*NH + k0 + lk];
            Asi[lk][m] = g_Fi[(m0 + m)*NH + k0 + lk];
            Bs [lk][m] = Bg[(n0 + m)*NH + k0 + lk];
        }
        __syncthreads();
#pragma unroll
        for (int k = 0; k < 16; k++) {
            float4 arv = *(const float4*)&Asr[k][tm*4];
            float4 aiv = *(const float4*)&Asi[k][tm*4];
            float4 bv  = *(const float4*)&Bs [k][tn*4];
            float ar[4] = {arv.x, arv.y, arv.z, arv.w};
            float ai[4] = {aiv.x, aiv.y, aiv.z, aiv.w};
            float bb[4] = {bv.x, bv.y, bv.z, bv.w};
#pragma unroll
            for (int i = 0; i < 4; i++)
#pragma unroll
                for (int j = 0; j < 4; j++) {
                    accR[i][j] += ar[i] * bb[j];
                    accI[i][j] += ai[i] * bb[j];
                }
        }
        __syncthreads();
    }
    float* Cr = g_Ar + img * NH * NH;
    float* Ci = g_Ai + img * NH * NH;
#pragma unroll
    for (int i = 0; i < 4; i++)
#pragma unroll
        for (int j = 0; j < 4; j++) {
            int m = m0 + tm*4 + i, n = n0 + tn*4 + j;
            Cr[m*NH + n] = accR[i][j];
            Ci[m*NH + n] = accI[i][j];
        }
}

// Stage2: Xf[img][u][v] = sum_w A[img][u][w] * F[v][w]   (complex x complex)
__global__ void k_stage2() {
    const int img = blockIdx.z;
    const int m0 = blockIdx.y * 64;   // u
    const int n0 = blockIdx.x * 64;   // v  (0..254)
    __shared__ __align__(16) float Asr[16][68], Asi[16][68], Bsr[16][68], Bsi[16][68];
    const float* Agr = g_Ar + img * NH * NH;
    const float* Agi = g_Ai + img * NH * NH;
    float accR[4][4] = {{0.f}}, accI[4][4] = {{0.f}};
    const int tid = threadIdx.x;
    const int tn = tid & 15, tm = tid >> 4;
    const int lk = tid & 15, lr = tid >> 4;
    for (int k0 = 0; k0 < NH; k0 += 16) {
#pragma unroll
        for (int r = 0; r < 4; r++) {
            int m = lr + r * 16;
            Asr[lk][m] = Agr[(m0 + m)*NH + k0 + lk];
            Asi[lk][m] = Agi[(m0 + m)*NH + k0 + lk];
            int n = n0 + m;
            float br = 0.f, bi = 0.f;
            if (n < NF) {
                br = g_Fr[n*NH + k0 + lk];
                bi = g_Fi[n*NH + k0 + lk];
            }
            Bsr[lk][m] = br;
            Bsi[lk][m] = bi;
        }
        __syncthreads();
#pragma unroll
        for (int k = 0; k < 16; k++) {
            float4 arv = *(const float4*)&Asr[k][tm*4];
            float4 aiv = *(const float4*)&Asi[k][tm*4];
            float4 brv = *(const float4*)&Bsr[k][tn*4];
            float4 biv = *(const float4*)&Bsi[k][tn*4];
            float ar[4] = {arv.x, arv.y, arv.z, arv.w};
            float ai[4] = {aiv.x, aiv.y, aiv.z, aiv.w};
            float br[4] = {brv.x, brv.y, brv.z, brv.w};
            float bi[4] = {biv.x, biv.y, biv.z, biv.w};
#pragma unroll
            for (int i = 0; i < 4; i++)
#pragma unroll
                for (int j = 0; j < 4; j++) {
                    accR[i][j] += ar[i]*br[j] - ai[i]*bi[j];
                    accI[i][j] += ar[i]*bi[j] + ai[i]*br[j];
                }
        }
        __syncthreads();
    }
    float* Cr = g_Xfr + img * NH * NF;
    float* Ci = g_Xfi + img * NH * NF;
#pragma unroll
    for (int i = 0; i < 4; i++)
#pragma unroll
        for (int j = 0; j < 4; j++) {
            int m = m0 + tm*4 + i, n = n0 + tn*4 + j;
            if (n < NF) {
                Cr[m*NF + n] = accR[i][j];
                Ci[m*NF + n] = accI[i][j];
            }
        }
}

// Stage3: St[img][w'][u] = sum_v (Xf[img][u][v]*Kh[c][u][v]) * G[w'][v]
// (pointwise Kh multiply fused into A-tile load; output stored transposed)
__global__ void k_stage3() {
    const int img = blockIdx.z;
    const int c = img & 15;
    const int m0 = blockIdx.y * 64;   // u
    const int n0 = blockIdx.x * 64;   // w'
    __shared__ __align__(16) float Asr[16][68], Asi[16][68], Bsr[16][68], Bsi[16][68];
    const float* Xr = g_Xfr + img * NH * NF;
    const float* Xi = g_Xfi + img * NH * NF;
    const float* Kr = g_Khr + c * NH * NF;
    const float* Ki = g_Khi + c * NH * NF;
    float accR[4][4] = {{0.f}}, accI[4][4] = {{0.f}};
    const int tid = threadIdx.x;
    const int tn = tid & 15, tm = tid >> 4;
    const int lk = tid & 15, lr = tid >> 4;
    for (int k0 = 0; k0 < 256; k0 += 16) {   // covers 255, last col padded
        int kk = k0 + lk;
        bool kok = (kk < NF);
#pragma unroll
        for (int r = 0; r < 4; r++) {
            int m = lr + r * 16;
            float yr = 0.f, yi = 0.f, gr = 0.f, gi = 0.f;
            if (kok) {
                int off = (m0 + m)*NF + kk;
                float xr = Xr[off], xi = Xi[off];
                float kr = Kr[off], ki = Ki[off];
                yr = xr*kr - xi*ki;
                yi = xr*ki + xi*kr;
                int goff = (n0 + m)*NF + kk;
                gr = g_Gr[goff];
                gi = g_Gi[goff];
            }
            Asr[lk][m] = yr; Asi[lk][m] = yi;
            Bsr[lk][m] = gr; Bsi[lk][m] = gi;
        }
        __syncthreads();
#pragma unroll
        for (int k = 0; k < 16; k++) {
            float4 arv = *(const float4*)&Asr[k][tm*4];
            float4 aiv = *(const float4*)&Asi[k][tm*4];
            float4 brv = *(const float4*)&Bsr[k][tn*4];
            float4 biv = *(const float4*)&Bsi[k][tn*4];
            float ar[4] = {arv.x, arv.y, arv.z, arv.w};
            float ai[4] = {aiv.x, aiv.y, aiv.z, aiv.w};
            float br[4] = {brv.x, brv.y, brv.z, brv.w};
            float bi[4] = {biv.x, biv.y, biv.z, biv.w};
#pragma unroll
            for (int i = 0; i < 4; i++)
#pragma unroll
                for (int j = 0; j < 4; j++) {
                    accR[i][j] += ar[i]*br[j] - ai[i]*bi[j];
                    accI[i][j] += ar[i]*bi[j] + ai[i]*br[j];
                }
        }
        __syncthreads();
    }
    float* Sr = g_Str + img * NH * NH;
    float* Si = g_Sti + img * NH * NH;
#pragma unroll
    for (int i = 0; i < 4; i++)
#pragma unroll
        for (int j = 0; j < 4; j++) {
            int u = m0 + tm*4 + i, w = n0 + tn*4 + j;
            Sr[w*NH + u] = accR[i][j];    // transposed store
            Si[w*NH + u] = accI[i][j];
        }
}

// Stage4: out[b][h][w][c] = bias[c] + sum_u (Er[h][u]*Str[w][u] - Ei[h][u]*Sti[w][u])
__global__ void k_stage4(const float* __restrict__ bias, float* __restrict__ out) {
    const int img = blockIdx.z;
    const int b = img >> 4, c = img & 15;
    const int m0 = blockIdx.y * 64;   // h
    const int n0 = blockIdx.x * 64;   // w
    __shared__ __align__(16) float Asr[16][68], Asi[16][68], Bsr[16][68], Bsi[16][68];
    const float* Sr = g_Str + img * NH * NH;
    const float* Si = g_Sti + img * NH * NH;
    float acc[4][4] = {{0.f}};
    const int tid = threadIdx.x;
    const int tn = tid & 15, tm = tid >> 4;
    const int lk = tid & 15, lr = tid >> 4;
    for (int k0 = 0; k0 < NH; k0 += 16) {
#pragma unroll
        for (int r = 0; r < 4; r++) {
            int m = lr + r * 16;
            Asr[lk][m] = g_Er[(m0 + m)*NH + k0 + lk];
            Asi[lk][m] = g_Ei[(m0 + m)*NH + k0 + lk];
            Bsr[lk][m] = Sr[(n0 + m)*NH + k0 + lk];
            Bsi[lk][m] = Si[(n0 + m)*NH + k0 + lk];
        }
        __syncthreads();
#pragma unroll
        for (int k = 0; k < 16; k++) {
            float4 arv = *(const float4*)&Asr[k][tm*4];
            float4 aiv = *(const float4*)&Asi[k][tm*4];
            float4 brv = *(const float4*)&Bsr[k][tn*4];
            float4 biv = *(const float4*)&Bsi[k][tn*4];
            float ar[4] = {arv.x, arv.y, arv.z, arv.w};
            float ai[4] = {aiv.x, aiv.y, aiv.z, aiv.w};
            float br[4] = {brv.x, brv.y, brv.z, brv.w};
            float bi[4] = {biv.x, biv.y, biv.z, biv.w};
#pragma unroll
            for (int i = 0; i < 4; i++)
#pragma unroll
                for (int j = 0; j < 4; j++) {
                    acc[i][j] += ar[i]*br[j] - ai[i]*bi[j];
                }
        }
        __syncthreads();
    }
    float bv = bias[c];
#pragma unroll
    for (int i = 0; i < 4; i++)
#pragma unroll
        for (int j = 0; j < 4; j++) {
            int h = m0 + tm*4 + i, w = n0 + tn*4 + j;
            out[((b*NH + h)*NH + w)*NC + c] = acc[i][j] + bv;
        }
}

// ---------------------------------------------------------------------------
extern "C" void kernel_launch(void* const* d_in, const int* in_sizes, int n_in,
                              void* d_out, int out_size) {
    const float* inp  = (const float*)d_in[0];
    const float* kr   = (const float*)d_in[1];
    const float* ki   = (const float*)d_in[2];
    const float* bias = (const float*)d_in[3];
    float* out = (float*)d_out;

    const int twN = NF*NH + NH*NF + NH*NH;          // 81664
    k_twiddles<<<(twN + 255) / 256, 256>>>();
    k_transpose<<<(NIMG*NH*NH + 255) / 256, 256>>>(inp);
    k_keff<<<(NF*NF*NC + 255) / 256, 256>>>(kr, ki);
    k_kh<<<(NC*NH*NF + 255) / 256, 256>>>();

    dim3 blk(256);
    dim3 g1(2, 2, NIMG); k_stage1<<<g1, blk>>>();
    dim3 g2(4, 2, NIMG); k_stage2<<<g2, blk>>>();
    dim3 g3(2, 2, NIMG); k_stage3<<<g3, blk>>>();
    dim3 g4(2, 2, NIMG); k_stage4<<<g4, blk>>>(bias, out);
}

// round 4
// speedup vs baseline: 1.0695x; 1.0667x over previous
#include <cuda_runtime.h>

#define NF 255
#define NH 128
#define NC 16
#define NIMG 64
#define PI2 6.28318530717958647692f
typedef unsigned long long u64;

__device__ __forceinline__ void fma2(u64 &d, u64 a, u64 b){
    asm("fma.rn.f32x2 %0, %1, %2, %0;" : "+l"(d) : "l"(a), "l"(b));
}
__device__ __forceinline__ u64 pk2(float lo, float hi){
    u64 r; asm("mov.b64 %0, {%1,%2};" : "=l"(r) : "f"(lo), "f"(hi)); return r;
}
__device__ __forceinline__ float2 up2(u64 v){
    float2 f; asm("mov.b64 {%0,%1}, %2;" : "=f"(f.x), "=f"(f.y) : "l"(v)); return f;
}

// scratch (device globals: allocation-free rule)
__device__ float2 g_Fp[NF*NH];          // (cos,-sin)[v*128+h]
__device__ float2 g_Gp[NH*NF];          // (cos, sin)[w'*255+v], crop +63
__device__ float2 g_E2r[NH*NH];         // (Er,Er)   Er=cu*cos
__device__ float2 g_E2n[NH*NH];         // (-Ei,-Ei) Ei=cu*sin
__device__ float  g_xT[NIMG*NH*NH];     // [img][w][h]
__device__ float2 g_A [NIMG*NH*NH];     // [img][u][w]
__device__ float2 g_Xf[NIMG*NH*NF];     // [img][u][v]
__device__ float2 g_Kh[NC*NH*NF];       // [c][u][v] folded, scaled
__device__ float2 g_St[NIMG*NH*NH];     // [img][w'][u] (transposed)

__global__ void k_twiddles(){
    int i = blockIdx.x*blockDim.x + threadIdx.x;
    const float w0 = PI2/255.0f;
    if(i < NF*NH){
        int v=i/NH, h=i%NH; float a=w0*(float)((v*h)%NF);
        g_Fp[i]=make_float2(cosf(a),-sinf(a)); return;
    }
    int j=i-NF*NH;
    if(j < NH*NF){
        int wq=j/NF, v=j%NF; float a=w0*(float)((v*(wq+63))%NF);
        g_Gp[j]=make_float2(cosf(a),sinf(a)); return;
    }
    int e=j-NH*NF;
    if(e < NH*NH){
        int h=e/NH, u=e%NH; float a=w0*(float)((u*(h+63))%NF);
        float cu = u?2.f:1.f, er=cu*cosf(a), ei=cu*sinf(a);
        g_E2r[e]=make_float2(er,er); g_E2n[e]=make_float2(-ei,-ei);
    }
}

// in[b][h][w][c] -> g_xT[(b*16+c)][w][h], smem-staged
__global__ void k_transpose(const float* __restrict__ in){
    __shared__ float ts[NC*16*36];
    const int b=blockIdx.z, h0=blockIdx.y*32, w0=blockIdx.x*16, tid=threadIdx.x;
#pragma unroll
    for(int it=0;it<2;it++){
        int p=tid+it*256, h=p>>4, w=p&15;
        const float4* src=(const float4*)(in+(size_t)((b*NH+h0+h)*NH+w0+w)*NC);
#pragma unroll
        for(int q=0;q<4;q++){
            float4 v=src[q]; int cb=q*4;
            ts[(cb+0)*576+w*36+h]=v.x; ts[(cb+1)*576+w*36+h]=v.y;
            ts[(cb+2)*576+w*36+h]=v.z; ts[(cb+3)*576+w*36+h]=v.w;
        }
    }
    __syncthreads();
    int h4=(tid&7)*4;
#pragma unroll
    for(int it=0;it<8;it++){
        int q=(tid>>3)+it*32, c=q>>4, w=q&15;
        float4 v=*(const float4*)&ts[c*576+w*36+h4];
        *(float4*)&g_xT[(size_t)((b*NC+c)*NH+w0+w)*NH+h0+h4]=v;
    }
}

// fused Keff (sum over cout) + Hermitian fold + 1/255^2 scale
__global__ void k_keffkh(const float* __restrict__ kr, const float* __restrict__ ki){
    int idx = blockIdx.x*blockDim.x + threadIdx.x;
    if(idx >= NH*NF*NC) return;
    int c = idx&15, v = (idx>>4)%NF, u = idx/(16*NF);
    int u2=(NF-u)%NF, v2=(NF-v)%NF;
    size_t p1=((size_t)(u*NF+v)*NC+c)*16, p2=((size_t)(u2*NF+v2)*NC+c)*16;
    float sr1=0,si1=0,sr2=0,si2=0; const float4* a;
    a=(const float4*)(kr+p1);
#pragma unroll
    for(int j=0;j<4;j++){float4 t=a[j];sr1+=t.x+t.y+t.z+t.w;}
    a=(const float4*)(ki+p1);
#pragma unroll
    for(int j=0;j<4;j++){float4 t=a[j];si1+=t.x+t.y+t.z+t.w;}
    a=(const float4*)(kr+p2);
#pragma unroll
    for(int j=0;j<4;j++){float4 t=a[j];sr2+=t.x+t.y+t.z+t.w;}
    a=(const float4*)(ki+p2);
#pragma unroll
    for(int j=0;j<4;j++){float4 t=a[j];si2+=t.x+t.y+t.z+t.w;}
    const float s = 0.5f/65025.0f;
    g_Kh[(c*NH+u)*NF+v]=make_float2(s*(sr1+sr2), s*(si1-si2));
}

// GEMM: BM=128, BN=64, BK=16, 256 thr, 8m x 4n packed microtile.
// A groups: 8 pairs(64B)+16B pad -> 20 f/group; B: 4 pairs(32B)+16B pad -> 12 f/group.
#define A_PITCH 324
#define B_PITCH 196
__device__ __forceinline__ int aoff(int k,int m){ return k*A_PITCH+(m>>3)*20+(m&7)*2; }
__device__ __forceinline__ int boff(int k,int n){ return k*B_PITCH+(n>>2)*12+(n&3)*2; }

__device__ __forceinline__ void cplx_inner(const float* ARR,const float* ANP,
        const float* BP,const float* BS, u64 (&acc)[8][4], int tm, int tn){
#pragma unroll 4
    for(int k=0;k<16;k++){
        u64 aR[8],aN[8],bP[4],bS[4];
        const ulonglong2* p1=(const ulonglong2*)&ARR[k*A_PITCH+tm*20];
        const ulonglong2* p2=(const ulonglong2*)&ANP[k*A_PITCH+tm*20];
        const ulonglong2* p3=(const ulonglong2*)&BP [k*B_PITCH+tn*12];
        const ulonglong2* p4=(const ulonglong2*)&BS [k*B_PITCH+tn*12];
#pragma unroll
        for(int q=0;q<4;q++){
            ulonglong2 t=p1[q]; aR[2*q]=t.x; aR[2*q+1]=t.y;
            ulonglong2 s=p2[q]; aN[2*q]=s.x; aN[2*q+1]=s.y;
        }
        { ulonglong2 t=p3[0]; bP[0]=t.x; bP[1]=t.y; t=p3[1]; bP[2]=t.x; bP[3]=t.y;
          t=p4[0]; bS[0]=t.x; bS[1]=t.y; t=p4[1]; bS[2]=t.x; bS[3]=t.y; }
#pragma unroll
        for(int i=0;i<8;i++)
#pragma unroll
            for(int j=0;j<4;j++){ fma2(acc[i][j],aR[i],bP[j]); fma2(acc[i][j],aN[i],bS[j]); }
    }
}

// Stage1: A[img][u][w] = sum_h F[u][h]*x[img][w][h]  (cplx x real)
__global__ void __launch_bounds__(256) k_stage1(){
    extern __shared__ float sm[];
    float* AP=sm; float* BD=sm+16*A_PITCH;
    const int img=blockIdx.z, n0=blockIdx.x*64, tid=threadIdx.x;
    const int tn=tid&15, tm=tid>>4, lk=tid&15, lr=tid>>4;
    const float* Bg = g_xT + img*NH*NH;
    u64 acc[8][4];
#pragma unroll
    for(int i=0;i<8;i++)
#pragma unroll
        for(int j=0;j<4;j++) acc[i][j]=0ULL;
    for(int k0=0;k0<NH;k0+=16){
#pragma unroll
        for(int r=0;r<8;r++){ int m=lr+r*16;
            *(float2*)&AP[aoff(lk,m)] = g_Fp[m*NH+k0+lk]; }
#pragma unroll
        for(int r=0;r<4;r++){ int n=lr+r*16;
            float x=Bg[(n0+n)*NH+k0+lk];
            *(float2*)&BD[boff(lk,n)] = make_float2(x,x); }
        __syncthreads();
#pragma unroll 4
        for(int k=0;k<16;k++){
            u64 aP[8],bD[4];
            const ulonglong2* p1=(const ulonglong2*)&AP[k*A_PITCH+tm*20];
            const ulonglong2* p3=(const ulonglong2*)&BD[k*B_PITCH+tn*12];
#pragma unroll
            for(int q=0;q<4;q++){ ulonglong2 t=p1[q]; aP[2*q]=t.x; aP[2*q+1]=t.y; }
            { ulonglong2 t=p3[0]; bD[0]=t.x; bD[1]=t.y; t=p3[1]; bD[2]=t.x; bD[3]=t.y; }
#pragma unroll
            for(int i=0;i<8;i++)
#pragma unroll
                for(int j=0;j<4;j++) fma2(acc[i][j],aP[i],bD[j]);
        }
        __syncthreads();
    }
    float2* C = g_A + img*NH*NH;
#pragma unroll
    for(int i=0;i<8;i++){ int m=tm*8+i;
#pragma unroll
        for(int j=0;j<4;j++) C[m*NH+n0+tn*4+j]=up2(acc[i][j]); }
}

// Stage2: Xf[img][u][v] = sum_w A[img][u][w]*F[v][w]  (cplx x cplx)
__global__ void __launch_bounds__(256) k_stage2(){
    extern __shared__ float sm[];
    float* ARR=sm; float* ANP=sm+16*A_PITCH;
    float* BP=sm+32*A_PITCH; float* BS=BP+16*B_PITCH;
    const int img=blockIdx.z, n0=blockIdx.x*64, tid=threadIdx.x;
    const int tn=tid&15, tm=tid>>4, lk=tid&15, lr=tid>>4;
    const float2* Ag = g_A + img*NH*NH;
    u64 acc[8][4];
#pragma unroll
    for(int i=0;i<8;i++)
#pragma unroll
        for(int j=0;j<4;j++) acc[i][j]=0ULL;
    for(int k0=0;k0<NH;k0+=16){
#pragma unroll
        for(int r=0;r<8;r++){ int m=lr+r*16;
            float2 a=Ag[m*NH+k0+lk];
            *(float2*)&ARR[aoff(lk,m)]=make_float2(a.x,a.x);
            *(float2*)&ANP[aoff(lk,m)]=make_float2(-a.y,a.y); }
#pragma unroll
        for(int r=0;r<4;r++){ int n=lr+r*16, v=n0+n;
            float2 b = (v<NF)? g_Fp[v*NH+k0+lk] : make_float2(0.f,0.f);
            *(float2*)&BP[boff(lk,n)]=b;
            *(float2*)&BS[boff(lk,n)]=make_float2(b.y,b.x); }
        __syncthreads();
        cplx_inner(ARR,ANP,BP,BS,acc,tm,tn);
        __syncthreads();
    }
    float2* C = g_Xf + img*NH*NF;
#pragma unroll
    for(int i=0;i<8;i++){ int m=tm*8+i;
#pragma unroll
        for(int j=0;j<4;j++){ int n=n0+tn*4+j;
            if(n<NF) C[m*NF+n]=up2(acc[i][j]); } }
}

// Stage3: St[img][w'][u] = sum_v (Xf[u][v]*Kh[c][u][v])*G[w'][v]
__global__ void __launch_bounds__(256) k_stage3(){
    extern __shared__ float sm[];
    float* ARR=sm; float* ANP=sm+16*A_PITCH;
    float* BP=sm+32*A_PITCH; float* BS=BP+16*B_PITCH;
    const int img=blockIdx.z, c=img&15, n0=blockIdx.x*64, tid=threadIdx.x;
    const int tn=tid&15, tm=tid>>4, lk=tid&15, lr=tid>>4;
    const float2* Xg = g_Xf + img*NH*NF;
    const float2* Kg = g_Kh + c*NH*NF;
    u64 acc[8][4];
#pragma unroll
    for(int i=0;i<8;i++)
#pragma unroll
        for(int j=0;j<4;j++) acc[i][j]=0ULL;
    for(int k0=0;k0<256;k0+=16){
        int kk=k0+lk; bool ok=(kk<NF);
#pragma unroll
        for(int r=0;r<8;r++){ int m=lr+r*16;
            float yr=0.f, yi=0.f;
            if(ok){ float2 x=Xg[m*NF+kk], h=Kg[m*NF+kk];
                yr=x.x*h.x-x.y*h.y; yi=x.x*h.y+x.y*h.x; }
            *(float2*)&ARR[aoff(lk,m)]=make_float2(yr,yr);
            *(float2*)&ANP[aoff(lk,m)]=make_float2(-yi,yi); }
#pragma unroll
        for(int r=0;r<4;r++){ int n=lr+r*16;
            float2 g = ok ? g_Gp[(n0+n)*NF+kk] : make_float2(0.f,0.f);
            *(float2*)&BP[boff(lk,n)]=g;
            *(float2*)&BS[boff(lk,n)]=make_float2(g.y,g.x); }
        __syncthreads();
        cplx_inner(ARR,ANP,BP,BS,acc,tm,tn);
        __syncthreads();
    }
    float2* C = g_St + img*NH*NH;
#pragma unroll
    for(int i=0;i<8;i++){ int m=tm*8+i;
#pragma unroll
        for(int j=0;j<4;j++){ int n=n0+tn*4+j;
            C[n*NH+m]=up2(acc[i][j]); } }   // transposed store
}

// Stage4: out = bias + sum_u (Er*Sr - Ei*Si), n-packed accumulators
__global__ void __launch_bounds__(256) k_stage4(const float* __restrict__ bias,
                                               float* __restrict__ out){
    extern __shared__ float sm[];
    float* AE=sm; float* AN=sm+16*A_PITCH;
    float* BR=sm+32*A_PITCH; float* BI=BR+16*68;
    const int img=blockIdx.z, b=img>>4, c=img&15, n0=blockIdx.x*64, tid=threadIdx.x;
    const int tn=tid&15, tm=tid>>4, lk=tid&15, lr=tid>>4;
    const float2* Sg = g_St + img*NH*NH;
    u64 acc[8][2];
#pragma unroll
    for(int i=0;i<8;i++){ acc[i][0]=0ULL; acc[i][1]=0ULL; }
    for(int k0=0;k0<NH;k0+=16){
#pragma unroll
        for(int r=0;r<8;r++){ int m=lr+r*16;
            *(float2*)&AE[aoff(lk,m)]=g_E2r[m*NH+k0+lk];
            *(float2*)&AN[aoff(lk,m)]=g_E2n[m*NH+k0+lk]; }
#pragma unroll
        for(int r=0;r<4;r++){ int n=lr+r*16;
            float2 s=Sg[(n0+n)*NH+k0+lk];
            BR[lk*68+n]=s.x; BI[lk*68+n]=s.y; }
        __syncthreads();
#pragma unroll 4
        for(int k=0;k<16;k++){
            u64 aE[8],aN2[8];
            const ulonglong2* p1=(const ulonglong2*)&AE[k*A_PITCH+tm*20];
            const ulonglong2* p2=(const ulonglong2*)&AN[k*A_PITCH+tm*20];
#pragma unroll
            for(int q=0;q<4;q++){
                ulonglong2 t=p1[q]; aE[2*q]=t.x; aE[2*q+1]=t.y;
                ulonglong2 s=p2[q]; aN2[2*q]=s.x; aN2[2*q+1]=s.y; }
            float4 br=*(const float4*)&BR[k*68+tn*4];
            float4 bi=*(const float4*)&BI[k*68+tn*4];
            u64 b0=pk2(br.x,br.y), b1=pk2(br.z,br.w);
            u64 c0=pk2(bi.x,bi.y), c1=pk2(bi.z,bi.w);
#pragma unroll
            for(int i=0;i<8;i++){
                fma2(acc[i][0],aE[i],b0); fma2(acc[i][0],aN2[i],c0);
                fma2(acc[i][1],aE[i],b1); fma2(acc[i][1],aN2[i],c1);
            }
        }
        __syncthreads();
    }
    float bv = bias[c];
#pragma unroll
    for(int i=0;i<8;i++){ int h=tm*8+i;
#pragma unroll
        for(int j2=0;j2<2;j2++){
            float2 p=up2(acc[i][j2]);
            int w=n0+tn*4+j2*2;
            out[((size_t)((b*NH+h)*NH+w  ))*NC+c]=p.x+bv;
            out[((size_t)((b*NH+h)*NH+w+1))*NC+c]=p.y+bv;
        } }
}

extern "C" void kernel_launch(void* const* d_in, const int* in_sizes, int n_in,
                              void* d_out, int out_size){
    const float* inp  = (const float*)d_in[0];
    const float* kr   = (const float*)d_in[1];
    const float* ki   = (const float*)d_in[2];
    const float* bias = (const float*)d_in[3];
    float* out = (float*)d_out;

    const int SM1  = (16*A_PITCH + 16*B_PITCH)*4;           // 33280
    const int SM23 = (32*A_PITCH + 32*B_PITCH)*4;           // 66560
    const int SM4  = (32*A_PITCH + 32*68)*4;                // 50176
    static bool attr_done = false;
    if(!attr_done){
        cudaFuncSetAttribute(k_stage2, cudaFuncAttributeMaxDynamicSharedMemorySize, SM23);
        cudaFuncSetAttribute(k_stage3, cudaFuncAttributeMaxDynamicSharedMemorySize, SM23);
        cudaFuncSetAttribute(k_stage4, cudaFuncAttributeMaxDynamicSharedMemorySize, SM4);
        attr_done = true;
    }

    const int twN = NF*NH + NH*NF + NH*NH;
    k_twiddles<<<(twN+255)/256, 256>>>();
    dim3 tg(8,4,4);
    k_transpose<<<tg, 256>>>(inp);
    k_keffkh<<<(NH*NF*NC+255)/256, 256>>>(kr, ki);

    dim3 blk(256);
    dim3 g1(2,1,NIMG); k_stage1<<<g1, blk, SM1 >>>();
    dim3 g2(4,1,NIMG); k_stage2<<<g2, blk, SM23>>>();
    dim3 g3(2,1,NIMG); k_stage3<<<g3, blk, SM23>>>();
    dim3 g4(2,1,NIMG); k_stage4<<<g4, blk, SM4 >>>(bias, out);
}

// round 5
// speedup vs baseline: 1.1444x; 1.0701x over previous
#include <cuda_runtime.h>

#define NF 255
#define NH 128
#define NC 16
#define NIMG 64
#define PI2 6.28318530717958647692f
typedef unsigned long long u64;

__device__ __forceinline__ void fma2(u64 &d, u64 a, u64 b){
    asm("fma.rn.f32x2 %0, %1, %2, %0;" : "+l"(d) : "l"(a), "l"(b));
}
__device__ __forceinline__ u64 pk2(float lo, float hi){
    u64 r; asm("mov.b64 %0, {%1,%2};" : "=l"(r) : "f"(lo), "f"(hi)); return r;
}
__device__ __forceinline__ float2 up2(u64 v){
    float2 f; asm("mov.b64 {%0,%1}, %2;" : "=f"(f.x), "=f"(f.y) : "l"(v)); return f;
}

// scratch (device globals: allocation-free rule)
__device__ float2 g_Fp[NF*NH];          // (cos,-sin)[v*128+h]
__device__ float2 g_Gp[NH*NF];          // (cos, sin)[w'*255+v], crop +63
__device__ float2 g_E2r[NH*NH];         // (Er,Er)   Er=cu*cos
__device__ float2 g_E2n[NH*NH];         // (-Ei,-Ei) Ei=cu*sin
__device__ float  g_xT[NIMG*NH*NH];     // [img][w][h]
__device__ float2 g_A [NIMG*NH*NH];     // [img][u][w]
__device__ float2 g_Xf[NIMG*NH*NF];     // [img][u][v]
__device__ float2 g_Kh[NC*NH*NF];       // [c][u][v] folded, scaled
__device__ float2 g_St[NIMG*NH*NH];     // [img][w'][u] (transposed)

__global__ void k_twiddles(){
    int i = blockIdx.x*blockDim.x + threadIdx.x;
    const float w0 = PI2/255.0f;
    if(i < NF*NH){
        int v=i/NH, h=i%NH; float a=w0*(float)((v*h)%NF);
        g_Fp[i]=make_float2(cosf(a),-sinf(a)); return;
    }
    int j=i-NF*NH;
    if(j < NH*NF){
        int wq=j/NF, v=j%NF; float a=w0*(float)((v*(wq+63))%NF);
        g_Gp[j]=make_float2(cosf(a),sinf(a)); return;
    }
    int e=j-NH*NF;
    if(e < NH*NH){
        int h=e/NH, u=e%NH; float a=w0*(float)((u*(h+63))%NF);
        float cu = u?2.f:1.f, er=cu*cosf(a), ei=cu*sinf(a);
        g_E2r[e]=make_float2(er,er); g_E2n[e]=make_float2(-ei,-ei);
    }
}

// in[b][h][w][c] -> g_xT[(b*16+c)][w][h], smem-staged
__global__ void k_transpose(const float* __restrict__ in){
    __shared__ float ts[NC*16*36];
    const int b=blockIdx.z, h0=blockIdx.y*32, w0=blockIdx.x*16, tid=threadIdx.x;
#pragma unroll
    for(int it=0;it<2;it++){
        int p=tid+it*256, h=p>>4, w=p&15;
        const float4* src=(const float4*)(in+(size_t)((b*NH+h0+h)*NH+w0+w)*NC);
#pragma unroll
        for(int q=0;q<4;q++){
            float4 v=src[q]; int cb=q*4;
            ts[(cb+0)*576+w*36+h]=v.x; ts[(cb+1)*576+w*36+h]=v.y;
            ts[(cb+2)*576+w*36+h]=v.z; ts[(cb+3)*576+w*36+h]=v.w;
        }
    }
    __syncthreads();
    int h4=(tid&7)*4;
#pragma unroll
    for(int it=0;it<8;it++){
        int q=(tid>>3)+it*32, c=q>>4, w=q&15;
        float4 v=*(const float4*)&ts[c*576+w*36+h4];
        *(float4*)&g_xT[(size_t)((b*NC+c)*NH+w0+w)*NH+h0+h4]=v;
    }
}

// fused Keff (sum over cout) + Hermitian fold + 1/255^2 scale
__global__ void k_keffkh(const float* __restrict__ kr, const float* __restrict__ ki){
    int idx = blockIdx.x*blockDim.x + threadIdx.x;
    if(idx >= NH*NF*NC) return;
    int c = idx&15, v = (idx>>4)%NF, u = idx/(16*NF);
    int u2=(NF-u)%NF, v2=(NF-v)%NF;
    size_t p1=((size_t)(u*NF+v)*NC+c)*16, p2=((size_t)(u2*NF+v2)*NC+c)*16;
    float sr1=0,si1=0,sr2=0,si2=0; const float4* a;
    a=(const float4*)(kr+p1);
#pragma unroll
    for(int j=0;j<4;j++){float4 t=a[j];sr1+=t.x+t.y+t.z+t.w;}
    a=(const float4*)(ki+p1);
#pragma unroll
    for(int j=0;j<4;j++){float4 t=a[j];si1+=t.x+t.y+t.z+t.w;}
    a=(const float4*)(kr+p2);
#pragma unroll
    for(int j=0;j<4;j++){float4 t=a[j];sr2+=t.x+t.y+t.z+t.w;}
    a=(const float4*)(ki+p2);
#pragma unroll
    for(int j=0;j<4;j++){float4 t=a[j];si2+=t.x+t.y+t.z+t.w;}
    const float s = 0.5f/65025.0f;
    g_Kh[(c*NH+u)*NF+v]=make_float2(s*(sr1+sr2), s*(si1-si2));
}

// ---------------------------------------------------------------------------
// GEMM: BM=64, BN=64, BK=16, 128 threads (4 warps), 8m x 4n packed microtile.
// A: 8 groups of 8 pairs(64B)+16B pad -> 20 f/group, pitch 164.
// B: 16 groups of 4 pairs(32B)+16B pad -> 12 f/group, pitch 196.
// tn = tid&15 (n-quad), tm = tid>>4 (m-octet, 0..7). Fill: lk=tid&15, lr=tid>>4.
// ---------------------------------------------------------------------------
#define A_PITCH 164
#define B_PITCH 196
__device__ __forceinline__ int aoff(int k,int m){ return k*A_PITCH+(m>>3)*20+(m&7)*2; }
__device__ __forceinline__ int boff(int k,int n){ return k*B_PITCH+(n>>2)*12+(n&3)*2; }

__device__ __forceinline__ void cplx_inner(const float* ARR,const float* ANP,
        const float* BP,const float* BS, u64 (&acc)[8][4], int tm, int tn){
#pragma unroll 4
    for(int k=0;k<16;k++){
        u64 aR[8],aN[8],bP[4],bS[4];
        const ulonglong2* p1=(const ulonglong2*)&ARR[k*A_PITCH+tm*20];
        const ulonglong2* p2=(const ulonglong2*)&ANP[k*A_PITCH+tm*20];
        const ulonglong2* p3=(const ulonglong2*)&BP [k*B_PITCH+tn*12];
        const ulonglong2* p4=(const ulonglong2*)&BS [k*B_PITCH+tn*12];
#pragma unroll
        for(int q=0;q<4;q++){
            ulonglong2 t=p1[q]; aR[2*q]=t.x; aR[2*q+1]=t.y;
            ulonglong2 s=p2[q]; aN[2*q]=s.x; aN[2*q+1]=s.y;
        }
        { ulonglong2 t=p3[0]; bP[0]=t.x; bP[1]=t.y; t=p3[1]; bP[2]=t.x; bP[3]=t.y;
          t=p4[0]; bS[0]=t.x; bS[1]=t.y; t=p4[1]; bS[2]=t.x; bS[3]=t.y; }
#pragma unroll
        for(int i=0;i<8;i++)
#pragma unroll
            for(int j=0;j<4;j++){ fma2(acc[i][j],aR[i],bP[j]); fma2(acc[i][j],aN[i],bS[j]); }
    }
}

// Stage1: A[img][u][w] = sum_h F[u][h]*x[img][w][h]  (cplx x real)
__global__ void __launch_bounds__(128) k_stage1(){
    extern __shared__ float sm[];
    float* AP=sm; float* BD=sm+16*A_PITCH;
    const int img=blockIdx.z, n0=blockIdx.x*64, m0=blockIdx.y*64, tid=threadIdx.x;
    const int tn=tid&15, tm=tid>>4, lk=tid&15, lr=tid>>4;
    const float* Bg = g_xT + img*NH*NH;
    u64 acc[8][4];
#pragma unroll
    for(int i=0;i<8;i++)
#pragma unroll
        for(int j=0;j<4;j++) acc[i][j]=0ULL;
    for(int k0=0;k0<NH;k0+=16){
#pragma unroll
        for(int r=0;r<8;r++){ int m=lr+r*8;
            *(float2*)&AP[aoff(lk,m)] = g_Fp[(m0+m)*NH+k0+lk]; }
#pragma unroll
        for(int r=0;r<8;r++){ int n=lr+r*8;
            float x=Bg[(n0+n)*NH+k0+lk];
            *(float2*)&BD[boff(lk,n)] = make_float2(x,x); }
        __syncthreads();
#pragma unroll 4
        for(int k=0;k<16;k++){
            u64 aP[8],bD[4];
            const ulonglong2* p1=(const ulonglong2*)&AP[k*A_PITCH+tm*20];
            const ulonglong2* p3=(const ulonglong2*)&BD[k*B_PITCH+tn*12];
#pragma unroll
            for(int q=0;q<4;q++){ ulonglong2 t=p1[q]; aP[2*q]=t.x; aP[2*q+1]=t.y; }
            { ulonglong2 t=p3[0]; bD[0]=t.x; bD[1]=t.y; t=p3[1]; bD[2]=t.x; bD[3]=t.y; }
#pragma unroll
            for(int i=0;i<8;i++)
#pragma unroll
                for(int j=0;j<4;j++) fma2(acc[i][j],aP[i],bD[j]);
        }
        __syncthreads();
    }
    float2* C = g_A + img*NH*NH;
#pragma unroll
    for(int i=0;i<8;i++){ int m=m0+tm*8+i;
#pragma unroll
        for(int j=0;j<4;j++) C[m*NH+n0+tn*4+j]=up2(acc[i][j]); }
}

// Stage2: Xf[img][u][v] = sum_w A[img][u][w]*F[v][w]  (cplx x cplx)
__global__ void __launch_bounds__(128) k_stage2(){
    extern __shared__ float sm[];
    float* ARR=sm; float* ANP=sm+16*A_PITCH;
    float* BP=sm+32*A_PITCH; float* BS=BP+16*B_PITCH;
    const int img=blockIdx.z, n0=blockIdx.x*64, m0=blockIdx.y*64, tid=threadIdx.x;
    const int tn=tid&15, tm=tid>>4, lk=tid&15, lr=tid>>4;
    const float2* Ag = g_A + img*NH*NH;
    u64 acc[8][4];
#pragma unroll
    for(int i=0;i<8;i++)
#pragma unroll
        for(int j=0;j<4;j++) acc[i][j]=0ULL;
    for(int k0=0;k0<NH;k0+=16){
#pragma unroll
        for(int r=0;r<8;r++){ int m=lr+r*8;
            float2 a=Ag[(m0+m)*NH+k0+lk];
            *(float2*)&ARR[aoff(lk,m)]=make_float2(a.x,a.x);
            *(float2*)&ANP[aoff(lk,m)]=make_float2(-a.y,a.y); }
#pragma unroll
        for(int r=0;r<8;r++){ int n=lr+r*8, v=n0+n;
            float2 b = (v<NF)? g_Fp[v*NH+k0+lk] : make_float2(0.f,0.f);
            *(float2*)&BP[boff(lk,n)]=b;
            *(float2*)&BS[boff(lk,n)]=make_float2(b.y,b.x); }
        __syncthreads();
        cplx_inner(ARR,ANP,BP,BS,acc,tm,tn);
        __syncthreads();
    }
    float2* C = g_Xf + img*NH*NF;
#pragma unroll
    for(int i=0;i<8;i++){ int m=m0+tm*8+i;
#pragma unroll
        for(int j=0;j<4;j++){ int n=n0+tn*4+j;
            if(n<NF) C[m*NF+n]=up2(acc[i][j]); } }
}

// Stage3: St[img][w'][u] = sum_v (Xf[u][v]*Kh[c][u][v])*G[w'][v]
__global__ void __launch_bounds__(128) k_stage3(){
    extern __shared__ float sm[];
    float* ARR=sm; float* ANP=sm+16*A_PITCH;
    float* BP=sm+32*A_PITCH; float* BS=BP+16*B_PITCH;
    const int img=blockIdx.z, c=img&15, n0=blockIdx.x*64, m0=blockIdx.y*64, tid=threadIdx.x;
    const int tn=tid&15, tm=tid>>4, lk=tid&15, lr=tid>>4;
    const float2* Xg = g_Xf + img*NH*NF;
    const float2* Kg = g_Kh + c*NH*NF;
    u64 acc[8][4];
#pragma unroll
    for(int i=0;i<8;i++)
#pragma unroll
        for(int j=0;j<4;j++) acc[i][j]=0ULL;
    for(int k0=0;k0<256;k0+=16){
        int kk=k0+lk; bool ok=(kk<NF);
#pragma unroll
        for(int r=0;r<8;r++){ int m=lr+r*8;
            float yr=0.f, yi=0.f;
            if(ok){ float2 x=Xg[(m0+m)*NF+kk], h=Kg[(m0+m)*NF+kk];
                yr=x.x*h.x-x.y*h.y; yi=x.x*h.y+x.y*h.x; }
            *(float2*)&ARR[aoff(lk,m)]=make_float2(yr,yr);
            *(float2*)&ANP[aoff(lk,m)]=make_float2(-yi,yi); }
#pragma unroll
        for(int r=0;r<8;r++){ int n=lr+r*8;
            float2 g = ok ? g_Gp[(n0+n)*NF+kk] : make_float2(0.f,0.f);
            *(float2*)&BP[boff(lk,n)]=g;
            *(float2*)&BS[boff(lk,n)]=make_float2(g.y,g.x); }
        __syncthreads();
        cplx_inner(ARR,ANP,BP,BS,acc,tm,tn);
        __syncthreads();
    }
    float2* C = g_St + img*NH*NH;
#pragma unroll
    for(int i=0;i<8;i++){ int m=m0+tm*8+i;
#pragma unroll
        for(int j=0;j<4;j++){ int n=n0+tn*4+j;
            C[n*NH+m]=up2(acc[i][j]); } }   // transposed store
}

// Stage4: out = bias + sum_u (Er*Sr - Ei*Si), n-packed accumulators
__global__ void __launch_bounds__(128) k_stage4(const float* __restrict__ bias,
                                               float* __restrict__ out){
    extern __shared__ float sm[];
    float* AE=sm; float* AN=sm+16*A_PITCH;
    float* BR=sm+32*A_PITCH; float* BI=BR+16*68;
    const int img=blockIdx.z, b=img>>4, c=img&15;
    const int n0=blockIdx.x*64, m0=blockIdx.y*64, tid=threadIdx.x;
    const int tn=tid&15, tm=tid>>4, lk=tid&15, lr=tid>>4;
    const float2* Sg = g_St + img*NH*NH;
    u64 acc[8][2];
#pragma unroll
    for(int i=0;i<8;i++){ acc[i][0]=0ULL; acc[i][1]=0ULL; }
    for(int k0=0;k0<NH;k0+=16){
#pragma unroll
        for(int r=0;r<8;r++){ int m=lr+r*8;
            *(float2*)&AE[aoff(lk,m)]=g_E2r[(m0+m)*NH+k0+lk];
            *(float2*)&AN[aoff(lk,m)]=g_E2n[(m0+m)*NH+k0+lk]; }
#pragma unroll
        for(int r=0;r<8;r++){ int n=lr+r*8;
            float2 s=Sg[(n0+n)*NH+k0+lk];
            BR[lk*68+n]=s.x; BI[lk*68+n]=s.y; }
        __syncthreads();
#pragma unroll 4
        for(int k=0;k<16;k++){
            u64 aE[8],aN2[8];
            const ulonglong2* p1=(const ulonglong2*)&AE[k*A_PITCH+tm*20];
            const ulonglong2* p2=(const ulonglong2*)&AN[k*A_PITCH+tm*20];
#pragma unroll
            for(int q=0;q<4;q++){
                ulonglong2 t=p1[q]; aE[2*q]=t.x; aE[2*q+1]=t.y;
                ulonglong2 s=p2[q]; aN2[2*q]=s.x; aN2[2*q+1]=s.y; }
            float4 br=*(const float4*)&BR[k*68+tn*4];
            float4 bi=*(const float4*)&BI[k*68+tn*4];
            u64 b0=pk2(br.x,br.y), b1=pk2(br.z,br.w);
            u64 c0=pk2(bi.x,bi.y), c1=pk2(bi.z,bi.w);
#pragma unroll
            for(int i=0;i<8;i++){
                fma2(acc[i][0],aE[i],b0); fma2(acc[i][0],aN2[i],c0);
                fma2(acc[i][1],aE[i],b1); fma2(acc[i][1],aN2[i],c1);
            }
        }
        __syncthreads();
    }
    float bv = bias[c];
#pragma unroll
    for(int i=0;i<8;i++){ int h=m0+tm*8+i;
#pragma unroll
        for(int j2=0;j2<2;j2++){
            float2 p=up2(acc[i][j2]);
            int w=n0+tn*4+j2*2;
            out[((size_t)((b*NH+h)*NH+w  ))*NC+c]=p.x+bv;
            out[((size_t)((b*NH+h)*NH+w+1))*NC+c]=p.y+bv;
        } }
}

extern "C" void kernel_launch(void* const* d_in, const int* in_sizes, int n_in,
                              void* d_out, int out_size){
    const float* inp  = (const float*)d_in[0];
    const float* kr   = (const float*)d_in[1];
    const float* ki   = (const float*)d_in[2];
    const float* bias = (const float*)d_in[3];
    float* out = (float*)d_out;

    const int SM1  = (16*A_PITCH + 16*B_PITCH)*4;   // 23040
    const int SM23 = (32*A_PITCH + 32*B_PITCH)*4;   // 46080
    const int SM4  = (32*A_PITCH + 32*68)*4;        // 29696

    const int twN = NF*NH + NH*NF + NH*NH;
    k_twiddles<<<(twN+255)/256, 256>>>();
    dim3 tg(8,4,4);
    k_transpose<<<tg, 256>>>(inp);
    k_keffkh<<<(NH*NF*NC+255)/256, 256>>>(kr, ki);

    dim3 blk(128);
    dim3 g1(2,2,NIMG); k_stage1<<<g1, blk, SM1 >>>();
    dim3 g2(4,2,NIMG); k_stage2<<<g2, blk, SM23>>>();
    dim3 g3(2,2,NIMG); k_stage3<<<g3, blk, SM23>>>();
    dim3 g4(2,2,NIMG); k_stage4<<<g4, blk, SM4 >>>(bias, out);
}

// round 9
// speedup vs baseline: 1.1876x; 1.0378x over previous
#include <cuda_runtime.h>

#define NF 255
#define NH 128
#define NC 16
#define NIMG 64
#define PI2 6.28318530717958647692f
typedef unsigned long long u64;

__device__ __forceinline__ void fma2(u64 &d, u64 a, u64 b){
    asm("fma.rn.f32x2 %0, %1, %2, %0;" : "+l"(d) : "l"(a), "l"(b));
}
__device__ __forceinline__ u64 pk2(float lo, float hi){
    u64 r; asm("mov.b64 %0, {%1,%2};" : "=l"(r) : "f"(lo), "f"(hi)); return r;
}
__device__ __forceinline__ float2 up2(u64 v){
    float2 f; asm("mov.b64 {%0,%1}, %2;" : "=f"(f.x), "=f"(f.y) : "l"(v)); return f;
}

// scratch (device globals: allocation-free rule)
__device__ float2 g_Fp[NF*NH];          // (cos,-sin)[v*128+h]
__device__ float2 g_Gp[NH*NF];          // (cos, sin)[w'*255+v], crop +63
__device__ float2 g_E2r[NH*NH];         // (Er,Er)   Er=cu*cos
__device__ float2 g_E2n[NH*NH];         // (-Ei,-Ei) Ei=cu*sin
__device__ float  g_xT[NIMG*NH*NH];     // [img][w][h]
__device__ float2 g_A [NIMG*NH*NH];     // [img][u][w]
__device__ float2 g_Xf[NIMG*NH*NF];     // [img][u][v]
__device__ float2 g_Kh[NC*NH*NF];       // [c][u][v] folded, scaled
__device__ float2 g_St[NIMG*NH*NH];     // [img][w'][u] (transposed)

__global__ void k_twiddles(){
    int i = blockIdx.x*blockDim.x + threadIdx.x;
    const float w0 = PI2/255.0f;
    if(i < NF*NH){
        int v=i/NH, h=i%NH; float a=w0*(float)((v*h)%NF);
        g_Fp[i]=make_float2(cosf(a),-sinf(a)); return;
    }
    int j=i-NF*NH;
    if(j < NH*NF){
        int wq=j/NF, v=j%NF; float a=w0*(float)((v*(wq+63))%NF);
        g_Gp[j]=make_float2(cosf(a),sinf(a)); return;
    }
    int e=j-NH*NF;
    if(e < NH*NH){
        int h=e/NH, u=e%NH; float a=w0*(float)((u*(h+63))%NF);
        float cu = u?2.f:1.f, er=cu*cosf(a), ei=cu*sinf(a);
        g_E2r[e]=make_float2(er,er); g_E2n[e]=make_float2(-ei,-ei);
    }
}

// in[b][h][w][c] -> g_xT[(b*16+c)][w][h], smem-staged
__global__ void k_transpose(const float* __restrict__ in){
    __shared__ float ts[NC*16*36];
    const int b=blockIdx.z, h0=blockIdx.y*32, w0=blockIdx.x*16, tid=threadIdx.x;
#pragma unroll
    for(int it=0;it<2;it++){
        int p=tid+it*256, h=p>>4, w=p&15;
        const float4* src=(const float4*)(in+(size_t)((b*NH+h0+h)*NH+w0+w)*NC);
#pragma unroll
        for(int q=0;q<4;q++){
            float4 v=src[q]; int cb=q*4;
            ts[(cb+0)*576+w*36+h]=v.x; ts[(cb+1)*576+w*36+h]=v.y;
            ts[(cb+2)*576+w*36+h]=v.z; ts[(cb+3)*576+w*36+h]=v.w;
        }
    }
    __syncthreads();
    int h4=(tid&7)*4;
#pragma unroll
    for(int it=0;it<8;it++){
        int q=(tid>>3)+it*32, c=q>>4, w=q&15;
        float4 v=*(const float4*)&ts[c*576+w*36+h4];
        *(float4*)&g_xT[(size_t)((b*NC+c)*NH+w0+w)*NH+h0+h4]=v;
    }
}

// fused Keff (sum over cout) + Hermitian fold + 1/255^2 scale
__global__ void k_keffkh(const float* __restrict__ kr, const float* __restrict__ ki){
    int idx = blockIdx.x*blockDim.x + threadIdx.x;
    if(idx >= NH*NF*NC) return;
    int c = idx&15, v = (idx>>4)%NF, u = idx/(16*NF);
    int u2=(NF-u)%NF, v2=(NF-v)%NF;
    size_t p1=((size_t)(u*NF+v)*NC+c)*16, p2=((size_t)(u2*NF+v2)*NC+c)*16;
    float sr1=0,si1=0,sr2=0,si2=0; const float4* a;
    a=(const float4*)(kr+p1);
#pragma unroll
    for(int j=0;j<4;j++){float4 t=a[j];sr1+=t.x+t.y+t.z+t.w;}
    a=(const float4*)(ki+p1);
#pragma unroll
    for(int j=0;j<4;j++){float4 t=a[j];si1+=t.x+t.y+t.z+t.w;}
    a=(const float4*)(kr+p2);
#pragma unroll
    for(int j=0;j<4;j++){float4 t=a[j];sr2+=t.x+t.y+t.z+t.w;}
    a=(const float4*)(ki+p2);
#pragma unroll
    for(int j=0;j<4;j++){float4 t=a[j];si2+=t.x+t.y+t.z+t.w;}
    const float s = 0.5f/65025.0f;
    g_Kh[(c*NH+u)*NF+v]=make_float2(s*(sr1+sr2), s*(si1-si2));
}

// ---------------------------------------------------------------------------
// GEMM: BM=64, BN=64, BK=16, 128 thr, 8m x 4n packed microtile.
// Single-buffer smem; next-tile globals prefetched into registers and issued
// before the compute phase so LDG latency overlaps fma2 issue.
// ---------------------------------------------------------------------------
#define A_PITCH 164
#define B_PITCH 196
__device__ __forceinline__ int aoff(int k,int m){ return k*A_PITCH+(m>>3)*20+(m&7)*2; }
__device__ __forceinline__ int boff(int k,int n){ return k*B_PITCH+(n>>2)*12+(n&3)*2; }

__device__ __forceinline__ void cplx_inner(const float* ARR,const float* ANP,
        const float* BP,const float* BS, u64 (&acc)[8][4], int tm, int tn){
#pragma unroll 4
    for(int k=0;k<16;k++){
        u64 aR[8],aN[8],bP[4],bS[4];
        const ulonglong2* p1=(const ulonglong2*)&ARR[k*A_PITCH+tm*20];
        const ulonglong2* p2=(const ulonglong2*)&ANP[k*A_PITCH+tm*20];
        const ulonglong2* p3=(const ulonglong2*)&BP [k*B_PITCH+tn*12];
        const ulonglong2* p4=(const ulonglong2*)&BS [k*B_PITCH+tn*12];
#pragma unroll
        for(int q=0;q<4;q++){
            ulonglong2 t=p1[q]; aR[2*q]=t.x; aR[2*q+1]=t.y;
            ulonglong2 s=p2[q]; aN[2*q]=s.x; aN[2*q+1]=s.y;
        }
        { ulonglong2 t=p3[0]; bP[0]=t.x; bP[1]=t.y; t=p3[1]; bP[2]=t.x; bP[3]=t.y;
          t=p4[0]; bS[0]=t.x; bS[1]=t.y; t=p4[1]; bS[2]=t.x; bS[3]=t.y; }
#pragma unroll
        for(int i=0;i<8;i++)
#pragma unroll
            for(int j=0;j<4;j++){ fma2(acc[i][j],aR[i],bP[j]); fma2(acc[i][j],aN[i],bS[j]); }
    }
}

// Stage1: A[img][u][w] = sum_h F[u][h]*x[img][w][h]  (cplx x real)
__global__ void __launch_bounds__(128) k_stage1(){
    __shared__ __align__(16) float AP[16*A_PITCH];
    __shared__ __align__(16) float BD[16*B_PITCH];
    const int img=blockIdx.z, n0=blockIdx.x*64, m0=blockIdx.y*64, tid=threadIdx.x;
    const int tn=tid&15, tm=tid>>4, lk=tid&15, lr=tid>>4;
    const float* Bg = g_xT + img*NH*NH;
    u64 acc[8][4];
#pragma unroll
    for(int i=0;i<8;i++)
#pragma unroll
        for(int j=0;j<4;j++) acc[i][j]=0ULL;
    float2 pa[8]; float pbx[8];
    // prologue loads for tile 0
#pragma unroll
    for(int r=0;r<8;r++) pa[r]=g_Fp[(m0+lr+r*8)*NH+lk];
#pragma unroll
    for(int r=0;r<8;r++) pbx[r]=Bg[(n0+lr+r*8)*NH+lk];
    for(int t=0;t<8;t++){
#pragma unroll
        for(int r=0;r<8;r++) *(float2*)&AP[aoff(lk,lr+r*8)]=pa[r];
#pragma unroll
        for(int r=0;r<8;r++) *(float2*)&BD[boff(lk,lr+r*8)]=make_float2(pbx[r],pbx[r]);
        __syncthreads();
        if(t<7){
            int k0=(t+1)*16;
#pragma unroll
            for(int r=0;r<8;r++) pa[r]=g_Fp[(m0+lr+r*8)*NH+k0+lk];
#pragma unroll
            for(int r=0;r<8;r++) pbx[r]=Bg[(n0+lr+r*8)*NH+k0+lk];
        }
#pragma unroll 4
        for(int k=0;k<16;k++){
            u64 aP[8],bD[4];
            const ulonglong2* p1=(const ulonglong2*)&AP[k*A_PITCH+tm*20];
            const ulonglong2* p3=(const ulonglong2*)&BD[k*B_PITCH+tn*12];
#pragma unroll
            for(int q=0;q<4;q++){ ulonglong2 t2=p1[q]; aP[2*q]=t2.x; aP[2*q+1]=t2.y; }
            { ulonglong2 t2=p3[0]; bD[0]=t2.x; bD[1]=t2.y; t2=p3[1]; bD[2]=t2.x; bD[3]=t2.y; }
#pragma unroll
            for(int i=0;i<8;i++)
#pragma unroll
                for(int j=0;j<4;j++) fma2(acc[i][j],aP[i],bD[j]);
        }
        __syncthreads();
    }
    float2* C = g_A + img*NH*NH;
#pragma unroll
    for(int i=0;i<8;i++){ int m=m0+tm*8+i;
#pragma unroll
        for(int j=0;j<4;j++) C[m*NH+n0+tn*4+j]=up2(acc[i][j]); }
}

// Stage2: Xf[img][u][v] = sum_w A[img][u][w]*F[v][w]  (cplx x cplx)
__global__ void __launch_bounds__(128) k_stage2(){
    __shared__ __align__(16) float ARR[16*A_PITCH];
    __shared__ __align__(16) float ANP[16*A_PITCH];
    __shared__ __align__(16) float BP [16*B_PITCH];
    __shared__ __align__(16) float BS [16*B_PITCH];
    const int img=blockIdx.z, n0=blockIdx.x*64, m0=blockIdx.y*64, tid=threadIdx.x;
    const int tn=tid&15, tm=tid>>4, lk=tid&15, lr=tid>>4;
    const float2* Ag = g_A + img*NH*NH;
    u64 acc[8][4];
#pragma unroll
    for(int i=0;i<8;i++)
#pragma unroll
        for(int j=0;j<4;j++) acc[i][j]=0ULL;
    float2 pa[8], pb[8];
#pragma unroll
    for(int r=0;r<8;r++) pa[r]=Ag[(m0+lr+r*8)*NH+lk];
#pragma unroll
    for(int r=0;r<8;r++){ int v=n0+lr+r*8;
        pb[r]=(v<NF)? g_Fp[v*NH+lk] : make_float2(0.f,0.f); }
    for(int t=0;t<8;t++){
#pragma unroll
        for(int r=0;r<8;r++){ int m=lr+r*8;
            *(float2*)&ARR[aoff(lk,m)]=make_float2(pa[r].x,pa[r].x);
            *(float2*)&ANP[aoff(lk,m)]=make_float2(-pa[r].y,pa[r].y); }
#pragma unroll
        for(int r=0;r<8;r++){ int n=lr+r*8;
            *(float2*)&BP[boff(lk,n)]=pb[r];
            *(float2*)&BS[boff(lk,n)]=make_float2(pb[r].y,pb[r].x); }
        __syncthreads();
        if(t<7){
            int k0=(t+1)*16;
#pragma unroll
            for(int r=0;r<8;r++) pa[r]=Ag[(m0+lr+r*8)*NH+k0+lk];
#pragma unroll
            for(int r=0;r<8;r++){ int v=n0+lr+r*8;
                pb[r]=(v<NF)? g_Fp[v*NH+k0+lk] : make_float2(0.f,0.f); }
        }
        cplx_inner(ARR,ANP,BP,BS,acc,tm,tn);
        __syncthreads();
    }
    float2* C = g_Xf + img*NH*NF;
#pragma unroll
    for(int i=0;i<8;i++){ int m=m0+tm*8+i;
#pragma unroll
        for(int j=0;j<4;j++){ int n=n0+tn*4+j;
            if(n<NF) C[m*NF+n]=up2(acc[i][j]); } }
}

// Stage3: St[img][w'][u] = sum_v (Xf[u][v]*Kh[c][u][v])*G[w'][v]
__global__ void __launch_bounds__(128) k_stage3(){
    __shared__ __align__(16) float ARR[16*A_PITCH];
    __shared__ __align__(16) float ANP[16*A_PITCH];
    __shared__ __align__(16) float BP [16*B_PITCH];
    __shared__ __align__(16) float BS [16*B_PITCH];
    const int img=blockIdx.z, c=img&15, n0=blockIdx.x*64, m0=blockIdx.y*64, tid=threadIdx.x;
    const int tn=tid&15, tm=tid>>4, lk=tid&15, lr=tid>>4;
    const float2* Xg = g_Xf + img*NH*NF;
    const float2* Kg = g_Kh + c*NH*NF;
    u64 acc[8][4];
#pragma unroll
    for(int i=0;i<8;i++)
#pragma unroll
        for(int j=0;j<4;j++) acc[i][j]=0ULL;
    float2 py[8], pb[8];
    {
        int kk=lk; bool ok=(kk<NF);
#pragma unroll
        for(int r=0;r<8;r++){
            float yr=0.f, yi=0.f;
            if(ok){ float2 x=Xg[(m0+lr+r*8)*NF+kk], h=Kg[(m0+lr+r*8)*NF+kk];
                yr=x.x*h.x-x.y*h.y; yi=x.x*h.y+x.y*h.x; }
            py[r]=make_float2(yr,yi);
        }
#pragma unroll
        for(int r=0;r<8;r++)
            pb[r]= ok ? g_Gp[(n0+lr+r*8)*NF+kk] : make_float2(0.f,0.f);
    }
    for(int t=0;t<16;t++){
#pragma unroll
        for(int r=0;r<8;r++){ int m=lr+r*8;
            *(float2*)&ARR[aoff(lk,m)]=make_float2(py[r].x,py[r].x);
            *(float2*)&ANP[aoff(lk,m)]=make_float2(-py[r].y,py[r].y); }
#pragma unroll
        for(int r=0;r<8;r++){ int n=lr+r*8;
            *(float2*)&BP[boff(lk,n)]=pb[r];
            *(float2*)&BS[boff(lk,n)]=make_float2(pb[r].y,pb[r].x); }
        __syncthreads();
        if(t<15){
            int kk=(t+1)*16+lk; bool ok=(kk<NF);
#pragma unroll
            for(int r=0;r<8;r++){
                float yr=0.f, yi=0.f;
                if(ok){ float2 x=Xg[(m0+lr+r*8)*NF+kk], h=Kg[(m0+lr+r*8)*NF+kk];
                    yr=x.x*h.x-x.y*h.y; yi=x.x*h.y+x.y*h.x; }
                py[r]=make_float2(yr,yi);
            }
#pragma unroll
            for(int r=0;r<8;r++)
                pb[r]= ok ? g_Gp[(n0+lr+r*8)*NF+kk] : make_float2(0.f,0.f);
        }
        cplx_inner(ARR,ANP,BP,BS,acc,tm,tn);
        __syncthreads();
    }
    float2* C = g_St + img*NH*NH;
#pragma unroll
    for(int i=0;i<8;i++){ int m=m0+tm*8+i;
#pragma unroll
        for(int j=0;j<4;j++){ int n=n0+tn*4+j;
            C[n*NH+m]=up2(acc[i][j]); } }   // transposed store
}

// Stage4: out = bias + sum_u (Er*Sr - Ei*Si)
__global__ void __launch_bounds__(128) k_stage4(const float* __restrict__ bias,
                                               float* __restrict__ out){
    __shared__ __align__(16) float AE[16*A_PITCH];
    __shared__ __align__(16) float AN[16*A_PITCH];
    __shared__ __align__(16) float BR[16*68];
    __shared__ __align__(16) float BI[16*68];
    const int img=blockIdx.z, b2=img>>4, c=img&15;
    const int n0=blockIdx.x*64, m0=blockIdx.y*64, tid=threadIdx.x;
    const int tn=tid&15, tm=tid>>4, lk=tid&15, lr=tid>>4;
    const float2* Sg = g_St + img*NH*NH;
    u64 acc[8][2];
#pragma unroll
    for(int i=0;i<8;i++){ acc[i][0]=0ULL; acc[i][1]=0ULL; }
    float2 pe[8], pn[8], ps[8];
#pragma unroll
    for(int r=0;r<8;r++){ int m=m0+lr+r*8;
        pe[r]=g_E2r[m*NH+lk]; pn[r]=g_E2n[m*NH+lk]; }
#pragma unroll
    for(int r=0;r<8;r++) ps[r]=Sg[(n0+lr+r*8)*NH+lk];
    for(int t=0;t<8;t++){
#pragma unroll
        for(int r=0;r<8;r++){ int m=lr+r*8;
            *(float2*)&AE[aoff(lk,m)]=pe[r];
            *(float2*)&AN[aoff(lk,m)]=pn[r]; }
#pragma unroll
        for(int r=0;r<8;r++){ int n=lr+r*8;
            BR[lk*68+n]=ps[r].x; BI[lk*68+n]=ps[r].y; }
        __syncthreads();
        if(t<7){
            int k0=(t+1)*16;
#pragma unroll
            for(int r=0;r<8;r++){ int m=m0+lr+r*8;
                pe[r]=g_E2r[m*NH+k0+lk]; pn[r]=g_E2n[m*NH+k0+lk]; }
#pragma unroll
            for(int r=0;r<8;r++) ps[r]=Sg[(n0+lr+r*8)*NH+k0+lk];
        }
#pragma unroll 4
        for(int k=0;k<16;k++){
            u64 aE[8],aN2[8];
            const ulonglong2* p1=(const ulonglong2*)&AE[k*A_PITCH+tm*20];
            const ulonglong2* p2=(const ulonglong2*)&AN[k*A_PITCH+tm*20];
#pragma unroll
            for(int q=0;q<4;q++){
                ulonglong2 t2=p1[q]; aE[2*q]=t2.x; aE[2*q+1]=t2.y;
                ulonglong2 s2=p2[q]; aN2[2*q]=s2.x; aN2[2*q+1]=s2.y; }
            float4 br=*(const float4*)&BR[k*68+tn*4];
            float4 bi=*(const float4*)&BI[k*68+tn*4];
            u64 b0=pk2(br.x,br.y), b1=pk2(br.z,br.w);
            u64 c0=pk2(bi.x,bi.y), c1=pk2(bi.z,bi.w);
#pragma unroll
            for(int i=0;i<8;i++){
                fma2(acc[i][0],aE[i],b0); fma2(acc[i][0],aN2[i],c0);
                fma2(acc[i][1],aE[i],b1); fma2(acc[i][1],aN2[i],c1);
            }
        }
        __syncthreads();
    }
    float bv = bias[c];
#pragma unroll
    for(int i=0;i<8;i++){ int h=m0+tm*8+i;
#pragma unroll
        for(int j2=0;j2<2;j2++){
            float2 p=up2(acc[i][j2]);
            int w=n0+tn*4+j2*2;
            out[((size_t)((b2*NH+h)*NH+w  ))*NC+c]=p.x+bv;
            out[((size_t)((b2*NH+h)*NH+w+1))*NC+c]=p.y+bv;
        } }
}

extern "C" void kernel_launch(void* const* d_in, const int* in_sizes, int n_in,
                              void* d_out, int out_size){
    const float* inp  = (const float*)d_in[0];
    const float* kr   = (const float*)d_in[1];
    const float* ki   = (const float*)d_in[2];
    const float* bias = (const float*)d_in[3];
    float* out = (float*)d_out;

    const int twN = NF*NH + NH*NF + NH*NH;
    k_twiddles<<<(twN+255)/256, 256>>>();
    dim3 tg(8,4,4);
    k_transpose<<<tg, 256>>>(inp);
    k_keffkh<<<(NH*NF*NC+255)/256, 256>>>(kr, ki);

    dim3 blk(128);
    dim3 g1(2,2,NIMG); k_stage1<<<g1, blk>>>();
    dim3 g2(4,2,NIMG); k_stage2<<<g2, blk>>>();
    dim3 g3(2,2,NIMG); k_stage3<<<g3, blk>>>();
    dim3 g4(2,2,NIMG); k_stage4<<<g4, blk>>>(bias, out);
}